// round 14
// baseline (speedup 1.0000x reference)
#include <cuda_runtime.h>
#include <cstdint>

#define TT 64
#define CC 128
#define HD 32
#define NTHREADS 256

// Bank rules (lane = 4*gid + tig):
//  A loads  arr[(m0+gid)*S + kk+tig]   -> S ≡ 4 (mod 32)
//  B loads  arr[(kk+tig)*S + n0+gid]   -> S ≡ 8 (mod 32)
//  B loads  arr[(n0+gid)*S + kk+tig]   -> S ≡ 4 (mod 32)
#define XHS 36     // x quarter tf32 [64][36]  (A)  extent 32 ✓
#define WHS 104    // W quarter tf32 [32][104] (B)  extent 96 ✓
#define SCS 68     // scores/probs [64][68] (A, overlays staging region)
#define QSS 36     // q tf32 [64][36]  (A)             extent 32 ✓
#define KSS 36     // k tf32 [64][36]  (B via n-major) extent 32 ✓
#define VTS 68     // vT tf32 [32][68] (B via n-major) extent 64 ✓

#define OFF_XH 0
#define OFF_WH (TT * XHS)                  // 2304
#define STAGE_WORDS (OFF_WH + 32 * WHS)    // 5632  (sc overlay 64*68=4352 fits)
#define OFF_Q  STAGE_WORDS                 // 5632
#define OFF_K  (OFF_Q + TT * QSS)          // 7936
#define OFF_VT (OFF_K + TT * KSS)          // 10240
#define SMEM_WORDS (OFF_VT + HD * VTS)     // 12416 words = 49664 B

__device__ __forceinline__ uint32_t f2tf(float f) {
    uint32_t u;
    asm("cvt.rna.tf32.f32 %0, %1;" : "=r"(u) : "f"(f));
    return u;
}
__device__ __forceinline__ void mma_tf32(float c[4],
                                         uint32_t a0, uint32_t a1, uint32_t a2, uint32_t a3,
                                         uint32_t b0, uint32_t b1) {
    asm("mma.sync.aligned.m16n8k8.row.col.f32.tf32.tf32.f32 "
        "{%0,%1,%2,%3},{%4,%5,%6,%7},{%8,%9},{%0,%1,%2,%3};"
        : "+f"(c[0]), "+f"(c[1]), "+f"(c[2]), "+f"(c[3])
        : "r"(a0), "r"(a1), "r"(a2), "r"(a3), "r"(b0), "r"(b1));
}

// Phase-2 balanced tile tables: per warp up to 2 groups (m-tile i, jstart, cnt).
// Covers all (i, j) with j <= 2i+1 (20 tiles), max 3 tiles/warp.
__constant__ int P2_I [8][2]   = {{3,-1},{3,-1},{3, 2},{2,-1},{2,-1},{1,-1},{1,-1},{0,-1}};
__constant__ int P2_J0[8][2]   = {{0, 0},{3, 0},{6, 0},{1, 0},{4, 0},{0, 0},{2, 0},{0, 0}};
__constant__ int P2_CT[8][2]   = {{3, 0},{3, 0},{2, 1},{3, 0},{2, 0},{2, 0},{2, 0},{2, 0}};

__global__ __launch_bounds__(NTHREADS, 4)
void head_attn_kernel(const float* __restrict__ x,
                      const float* __restrict__ Wq,
                      const float* __restrict__ Wk,
                      const float* __restrict__ Wv,
                      float* __restrict__ out) {
    extern __shared__ float smem[];
    uint32_t* xh  = reinterpret_cast<uint32_t*>(smem + OFF_XH);  // x quarter tf32
    uint32_t* Wh  = reinterpret_cast<uint32_t*>(smem + OFF_WH);  // W quarter tf32
    uint32_t* qu  = reinterpret_cast<uint32_t*>(smem + OFF_Q);   // q tf32 [seq][d]
    uint32_t* ku  = reinterpret_cast<uint32_t*>(smem + OFF_K);   // k tf32 [seq][d]
    uint32_t* vT  = reinterpret_cast<uint32_t*>(smem + OFF_VT);  // vT tf32 [d][seq]
    uint32_t* scb = xh;   // scores/probs overlay staging region, stride SCS

    const int tid  = threadIdx.x;
    const int warp = tid >> 5;
    const int lane = tid & 31;
    const int gid  = lane >> 2;   // 0..7
    const int tig  = lane & 3;    // 0..3
    const int b    = blockIdx.x;
    const float* xb = x + (size_t)b * (TT * CC);

    // ---------------- Phase 1: QKV via tf32 MMA, 4-stage K-quarter staging (R11) ----------------
    {
        const int m0    = (warp & 3) * 16;
        const int nbase = (warp >> 2) * 48;

        float acc[6][4];
        #pragma unroll
        for (int j = 0; j < 6; j++)
            #pragma unroll
            for (int t = 0; t < 4; t++) acc[j][t] = 0.0f;

        #pragma unroll
        for (int s = 0; s < 4; s++) {
            if (s) __syncthreads();

            #pragma unroll
            for (int ii = 0; ii < (TT * 32) / 4 / NTHREADS; ii++) {   // 2
                int i = tid + ii * NTHREADS;
                int idx = i * 4;
                int r = idx >> 5, c = idx & 31;
                float4 v4 = *reinterpret_cast<const float4*>(xb + r * CC + 32 * s + c);
                *reinterpret_cast<uint4*>(xh + r * XHS + c) =
                    make_uint4(f2tf(v4.x), f2tf(v4.y), f2tf(v4.z), f2tf(v4.w));
            }
            {
                int i = tid;                                          // 1 iter
                int idx = i * 4;
                int dd = idx >> 5, c = idx & 31;
                int gi = ((32 * s + dd) * HD + c) / 4;
                float4 vq = reinterpret_cast<const float4*>(Wq)[gi];
                float4 vk = reinterpret_cast<const float4*>(Wk)[gi];
                float4 vv = reinterpret_cast<const float4*>(Wv)[gi];
                *reinterpret_cast<uint4*>(Wh + dd * WHS + c) =
                    make_uint4(f2tf(vq.x), f2tf(vq.y), f2tf(vq.z), f2tf(vq.w));
                *reinterpret_cast<uint4*>(Wh + dd * WHS + 32 + c) =
                    make_uint4(f2tf(vk.x), f2tf(vk.y), f2tf(vk.z), f2tf(vk.w));
                *reinterpret_cast<uint4*>(Wh + dd * WHS + 64 + c) =
                    make_uint4(f2tf(vv.x), f2tf(vv.y), f2tf(vv.z), f2tf(vv.w));
            }
            __syncthreads();

            #pragma unroll
            for (int kk = 0; kk < 32; kk += 8) {
                uint32_t a0 = xh[(m0 + gid)     * XHS + kk + tig];
                uint32_t a1 = xh[(m0 + gid + 8) * XHS + kk + tig];
                uint32_t a2 = xh[(m0 + gid)     * XHS + kk + tig + 4];
                uint32_t a3 = xh[(m0 + gid + 8) * XHS + kk + tig + 4];
                #pragma unroll
                for (int j = 0; j < 6; j++) {
                    int n0 = nbase + 8 * j;
                    uint32_t b0 = Wh[(kk + tig)     * WHS + n0 + gid];
                    uint32_t b1 = Wh[(kk + tig + 4) * WHS + n0 + gid];
                    mma_tf32(acc[j], a0, a1, a2, a3, b0, b1);
                }
            }
        }

        #pragma unroll
        for (int j = 0; j < 6; j++) {
            int n0 = nbase + 8 * j;
            int c  = n0 + 2 * tig;
            #pragma unroll
            for (int half = 0; half < 2; half++) {
                int row = m0 + gid + 8 * half;
                uint32_t u0 = f2tf(acc[j][2 * half]);
                uint32_t u1 = f2tf(acc[j][2 * half + 1]);
                if (n0 < 32) {
                    qu[row * QSS + c]     = u0;
                    qu[row * QSS + c + 1] = u1;
                } else if (n0 < 64) {
                    ku[row * KSS + (c - 32)] = u0;
                    ku[row * KSS + (c - 31)] = u1;
                } else {
                    vT[(c - 64) * VTS + row] = u0;
                    vT[(c - 63) * VTS + row] = u1;
                }
            }
        }
    }
    __syncthreads();

    // ---------------- Phase 2: scores, balanced tile table (max 3 tiles/warp) ----------------
    {
        const float scale = 0.17677669529663687f;   // 1/sqrt(32)
        #pragma unroll
        for (int g = 0; g < 2; g++) {
            int i   = P2_I[warp][g];
            int cnt = P2_CT[warp][g];
            if (i < 0 || cnt == 0) continue;
            int m0 = 16 * i;
            int j0 = P2_J0[warp][g];

            float acc[3][4];
            #pragma unroll
            for (int t = 0; t < 3; t++)
                #pragma unroll
                for (int e = 0; e < 4; e++) acc[t][e] = 0.0f;

            for (int k0 = 0; k0 < HD; k0 += 8) {
                uint32_t a0 = qu[(m0 + gid)     * QSS + k0 + tig];
                uint32_t a1 = qu[(m0 + gid + 8) * QSS + k0 + tig];
                uint32_t a2 = qu[(m0 + gid)     * QSS + k0 + tig + 4];
                uint32_t a3 = qu[(m0 + gid + 8) * QSS + k0 + tig + 4];
                for (int t = 0; t < cnt; t++) {
                    int n0 = 8 * (j0 + t);
                    uint32_t b0 = ku[(n0 + gid) * KSS + k0 + tig];
                    uint32_t b1 = ku[(n0 + gid) * KSS + k0 + tig + 4];
                    mma_tf32(acc[t], a0, a1, a2, a3, b0, b1);
                }
            }

            for (int t = 0; t < cnt; t++) {
                int n0 = 8 * (j0 + t);
                int c  = n0 + 2 * tig;
                #pragma unroll
                for (int half = 0; half < 2; half++) {
                    int row = m0 + gid + 8 * half;
                    scb[row * SCS + c]     = __float_as_uint(acc[t][2 * half]     * scale);
                    scb[row * SCS + c + 1] = __float_as_uint(acc[t][2 * half + 1] * scale);
                }
            }
        }
    }
    __syncthreads();

    // ---------------- Phase 3: softmax, 4 threads per row, single pass ----------------
    {
        const int r  = tid >> 2;      // row 0..63
        const int qd = tid & 3;       // quarter 0..3, cols qd*16..qd*16+15
        uint32_t* rowp = scb + r * SCS + qd * 16;
        const int base = qd * 16;

        float v[16];
        #pragma unroll
        for (int u = 0; u < 4; u++) {
            uint4 w4 = *reinterpret_cast<const uint4*>(rowp + 4 * u);
            v[4*u+0] = __uint_as_float(w4.x);
            v[4*u+1] = __uint_as_float(w4.y);
            v[4*u+2] = __uint_as_float(w4.z);
            v[4*u+3] = __uint_as_float(w4.w);
        }
        // causal mask
        #pragma unroll
        for (int u = 0; u < 16; u++)
            if (base + u > r) v[u] = -1e30f;

        float m = v[0];
        #pragma unroll
        for (int u = 1; u < 16; u++) m = fmaxf(m, v[u]);
        m = fmaxf(m, __shfl_xor_sync(0xffffffffu, m, 1));
        m = fmaxf(m, __shfl_xor_sync(0xffffffffu, m, 2));

        float e[16], sum = 0.0f;
        #pragma unroll
        for (int u = 0; u < 16; u++) {
            e[u] = (base + u <= r) ? __expf(v[u] - m) : 0.0f;
            sum += e[u];
        }
        sum += __shfl_xor_sync(0xffffffffu, sum, 1);
        sum += __shfl_xor_sync(0xffffffffu, sum, 2);
        float inv = 1.0f / sum;

        #pragma unroll
        for (int u = 0; u < 4; u++) {
            uint4 w4 = make_uint4(f2tf(e[4*u+0] * inv), f2tf(e[4*u+1] * inv),
                                  f2tf(e[4*u+2] * inv), f2tf(e[4*u+3] * inv));
            *reinterpret_cast<uint4*>(rowp + 4 * u) = w4;
        }
    }
    __syncthreads();

    // ---------------- Phase 4: out = P @ V, perfectly balanced (10 k-steps/warp) ----------------
    {
        const int nt = warp & 3;                    // n-tile 0..3 (cols 8nt..8nt+7)
        const int i1 = (warp < 4) ? 3 : 2;          // heavy m-tile
        const int i2 = (warp < 4) ? 0 : 1;          // light m-tile
        float* ob = out + (size_t)b * (TT * HD);

        #pragma unroll
        for (int p = 0; p < 2; p++) {
            int i  = p ? i2 : i1;
            int m0 = 16 * i;
            int n0 = 8 * nt;

            float acc[4] = {0.f, 0.f, 0.f, 0.f};
            const int kend = 16 * i + 8;   // probs beyond are exact zeros
            for (int k0 = 0; k0 <= kend; k0 += 8) {
                uint32_t a0 = scb[(m0 + gid)     * SCS + k0 + tig];
                uint32_t a1 = scb[(m0 + gid + 8) * SCS + k0 + tig];
                uint32_t a2 = scb[(m0 + gid)     * SCS + k0 + tig + 4];
                uint32_t a3 = scb[(m0 + gid + 8) * SCS + k0 + tig + 4];
                uint32_t b0 = vT[(n0 + gid) * VTS + k0 + tig];
                uint32_t b1 = vT[(n0 + gid) * VTS + k0 + tig + 4];
                mma_tf32(acc, a0, a1, a2, a3, b0, b1);
            }

            int c = n0 + 2 * tig;
            #pragma unroll
            for (int half = 0; half < 2; half++) {
                int row = m0 + gid + 8 * half;
                *reinterpret_cast<float2*>(ob + row * HD + c) =
                    make_float2(acc[2 * half], acc[2 * half + 1]);
            }
        }
    }
}

extern "C" void kernel_launch(void* const* d_in, const int* in_sizes, int n_in,
                              void* d_out, int out_size) {
    const float* x  = (const float*)d_in[0];
    const float* Wq = (const float*)d_in[1];
    const float* Wk = (const float*)d_in[2];
    const float* Wv = (const float*)d_in[3];
    float* out = (float*)d_out;

    const int B = in_sizes[0] / (TT * CC);   // 4096
    const size_t smem_bytes = SMEM_WORDS * sizeof(float);

    static_assert(4 * (SMEM_WORDS * sizeof(float) + 1024) <= 228 * 1024,
                  "4 CTAs/SM incl. per-CTA reserve");
    cudaFuncSetAttribute(head_attn_kernel,
                         cudaFuncAttributeMaxDynamicSharedMemorySize,
                         (int)smem_bytes);

    head_attn_kernel<<<B, NTHREADS, smem_bytes>>>(x, Wq, Wk, Wv, out);
}

// round 15
// speedup vs baseline: 1.0753x; 1.0753x over previous
#include <cuda_runtime.h>
#include <cstdint>

#define TT 64
#define CC 128
#define HD 32
#define NTHREADS 256

// Bank rules (lane = 4*gid + tig):
//  A loads  arr[(m0+gid)*S + kk+tig]   -> S mod 32 in {4,8,12,20,28,...}: 20 ok (20*gid+tig distinct)
//  B loads  arr[(kk+tig)*S + n0+gid]   -> S ≡ 8 (mod 32)
//  B loads  arr[(n0+gid)*S + kk+tig]   -> S ≡ 4 (mod 32)
#define XHS 20     // x stage fp32-raw [64][20]   (A)  extent 16 ✓
#define WHS 104    // W stage tf32 [16][104]      (B)  extent 96 ✓
#define SCS 68     // scores/probs [64][68] (A, overlays stage buffers)
#define QSS 36     // q tf32 [64][36]  (A)             extent 32 ✓
#define KSS 36     // k tf32 [64][36]  (B via n-major) extent 32 ✓
#define VTS 68     // vT tf32 [32][68] (B via n-major) extent 64 ✓

#define XW  (TT * XHS)        // 1280 words per x stage buffer
#define WW  (16 * WHS)        // 1664 words per W stage buffer
#define BUFW (XW + WW)        // 2944

#define OFF_B0X 0
#define OFF_B0W XW                       // 1280
#define OFF_B1X BUFW                     // 2944
#define OFF_B1W (BUFW + XW)              // 4224
#define OFF_Q   (2 * BUFW)               // 5888  (sc overlay 64*68=4352 fits below)
#define OFF_K   (OFF_Q + TT * QSS)       // 8192
#define OFF_VT  (OFF_K + TT * KSS)       // 10496
#define SMEM_WORDS (OFF_VT + HD * VTS)   // 12672 words = 50688 B

// W pre-converted to tf32, [128][104] (q|k|v, cols 96-103 zero pad)
__device__ uint32_t g_Wtf[CC * WHS];

__device__ __forceinline__ uint32_t f2tf(float f) {
    uint32_t u;
    asm("cvt.rna.tf32.f32 %0, %1;" : "=r"(u) : "f"(f));
    return u;
}
__device__ __forceinline__ uint32_t smem_u32(const void* p) {
    uint32_t a;
    asm("{ .reg .u64 t; cvta.to.shared.u64 t, %1; cvt.u32.u64 %0, t; }"
        : "=r"(a) : "l"(p));
    return a;
}
__device__ __forceinline__ void cp_async16(uint32_t dst, const void* src) {
    asm volatile("cp.async.ca.shared.global [%0], [%1], 16;"
                 :: "r"(dst), "l"(src));
}
__device__ __forceinline__ void cp_commit() {
    asm volatile("cp.async.commit_group;");
}
__device__ __forceinline__ void cp_wait_all() {
    asm volatile("cp.async.wait_group 0;");
}
__device__ __forceinline__ void mma_tf32(float c[4],
                                         uint32_t a0, uint32_t a1, uint32_t a2, uint32_t a3,
                                         uint32_t b0, uint32_t b1) {
    asm("mma.sync.aligned.m16n8k8.row.col.f32.tf32.tf32.f32 "
        "{%0,%1,%2,%3},{%4,%5,%6,%7},{%8,%9},{%0,%1,%2,%3};"
        : "+f"(c[0]), "+f"(c[1]), "+f"(c[2]), "+f"(c[3])
        : "r"(a0), "r"(a1), "r"(a2), "r"(a3), "r"(b0), "r"(b1));
}

// Pre-kernel: tf32-convert W into [128][104] global.
__global__ void wtf_kernel(const float* __restrict__ Wq,
                           const float* __restrict__ Wk,
                           const float* __restrict__ Wv) {
    int i = blockIdx.x * 256 + threadIdx.x;    // 52*256 = 13312 = 128*104
    int d = i / WHS, c = i % WHS;
    uint32_t u = 0;
    if (c < 32)       u = f2tf(Wq[d * HD + c]);
    else if (c < 64)  u = f2tf(Wk[d * HD + (c - 32)]);
    else if (c < 96)  u = f2tf(Wv[d * HD + (c - 64)]);
    g_Wtf[i] = u;
}

__global__ __launch_bounds__(NTHREADS, 4)
void head_attn_kernel(const float* __restrict__ x,
                      float* __restrict__ out) {
    extern __shared__ float smem[];
    uint32_t* qu  = reinterpret_cast<uint32_t*>(smem + OFF_Q);   // q tf32 [seq][d]
    uint32_t* ku  = reinterpret_cast<uint32_t*>(smem + OFF_K);   // k tf32 [seq][d]
    uint32_t* vT  = reinterpret_cast<uint32_t*>(smem + OFF_VT);  // vT tf32 [d][seq]
    uint32_t* scb = reinterpret_cast<uint32_t*>(smem);           // scores/probs overlay

    const int tid  = threadIdx.x;
    const int warp = tid >> 5;
    const int lane = tid & 31;
    const int gid  = lane >> 2;   // 0..7
    const int tig  = lane & 3;    // 0..3
    const int b    = blockIdx.x;
    const float* xb = x + (size_t)b * (TT * CC);

    uint32_t xoff[2] = { smem_u32(smem + OFF_B0X), smem_u32(smem + OFF_B1X) };
    uint32_t woff[2] = { smem_u32(smem + OFF_B0W), smem_u32(smem + OFF_B1W) };

    // ---------------- Phase 1: QKV, 8-stage K=16 double-buffered cp.async pipeline ----------------
    // M=64, N=96. warp: m-tile = warp&3, n-tiles = 6*(warp>>2)+0..5
    {
        const int m0    = (warp & 3) * 16;
        const int nbase = (warp >> 2) * 48;

        float acc[6][4];
        #pragma unroll
        for (int j = 0; j < 6; j++)
            #pragma unroll
            for (int t = 0; t < 4; t++) acc[j][t] = 0.0f;

        // x-stage thread mapping: r = tid>>2, c = (tid&3)*4 (one 16B copy/thread)
        const int xr = tid >> 2;
        const int xc = (tid & 3) * 4;

        // prologue: load stage 0 into buffer 0
        {
            cp_async16(xoff[0] + (xr * XHS + xc) * 4, xb + xr * CC + xc);
            cp_async16(woff[0] + tid * 16, g_Wtf + tid * 4);
            if (tid < 160)
                cp_async16(woff[0] + (tid + 256) * 16, g_Wtf + (tid + 256) * 4);
            cp_commit();
        }

        #pragma unroll
        for (int s = 0; s < 8; s++) {
            const int cur = s & 1;
            cp_wait_all();        // stage s data resident
            __syncthreads();      // visible to all; all warps done with buffer cur from stage s-2

            if (s < 7) {          // prefetch stage s+1 into other buffer (overlaps compute)
                const int nxt = cur ^ 1;
                cp_async16(xoff[nxt] + (xr * XHS + xc) * 4,
                           xb + xr * CC + 16 * (s + 1) + xc);
                const uint32_t* wsrc = g_Wtf + (s + 1) * 16 * WHS;
                cp_async16(woff[nxt] + tid * 16, wsrc + tid * 4);
                if (tid < 160)
                    cp_async16(woff[nxt] + (tid + 256) * 16, wsrc + (tid + 256) * 4);
                cp_commit();
            }

            const uint32_t* xh = reinterpret_cast<const uint32_t*>(smem) +
                                 (cur ? OFF_B1X : OFF_B0X);
            const uint32_t* Wh = reinterpret_cast<const uint32_t*>(smem) +
                                 (cur ? OFF_B1W : OFF_B0W);

            #pragma unroll
            for (int kk = 0; kk < 16; kk += 8) {
                uint32_t a0 = xh[(m0 + gid)     * XHS + kk + tig];
                uint32_t a1 = xh[(m0 + gid + 8) * XHS + kk + tig];
                uint32_t a2 = xh[(m0 + gid)     * XHS + kk + tig + 4];
                uint32_t a3 = xh[(m0 + gid + 8) * XHS + kk + tig + 4];
                #pragma unroll
                for (int j = 0; j < 6; j++) {
                    int n0 = nbase + 8 * j;
                    uint32_t b0 = Wh[(kk + tig)     * WHS + n0 + gid];
                    uint32_t b1 = Wh[(kk + tig + 4) * WHS + n0 + gid];
                    mma_tf32(acc[j], a0, a1, a2, a3, b0, b1);
                }
            }
        }

        // scatter as tf32: n<32 -> q [seq][d]; 32..63 -> k [seq][d]; >=64 -> vT [d][seq]
        #pragma unroll
        for (int j = 0; j < 6; j++) {
            int n0 = nbase + 8 * j;
            int c  = n0 + 2 * tig;
            #pragma unroll
            for (int half = 0; half < 2; half++) {
                int row = m0 + gid + 8 * half;
                uint32_t u0 = f2tf(acc[j][2 * half]);
                uint32_t u1 = f2tf(acc[j][2 * half + 1]);
                if (n0 < 32) {
                    qu[row * QSS + c]     = u0;
                    qu[row * QSS + c + 1] = u1;
                } else if (n0 < 64) {
                    ku[row * KSS + (c - 32)] = u0;
                    ku[row * KSS + (c - 31)] = u1;
                } else {
                    vT[(c - 64) * VTS + row] = u0;
                    vT[(c - 63) * VTS + row] = u1;
                }
            }
        }
    }
    __syncthreads();

    // ---------------- Phase 2: scores via tf32 MMA (R11 verbatim) ----------------
    {
        const int i  = warp & 3;
        const int m0 = 16 * i;
        const int jb = warp >> 2;
        int jn[4], cnt = 0;
        #pragma unroll
        for (int t = 0; t < 4; t++) {
            int j = jb + 2 * t;
            if (j <= 2 * i + 1) jn[cnt++] = j;
        }

        float acc[4][4];
        #pragma unroll
        for (int t = 0; t < 4; t++)
            #pragma unroll
            for (int e = 0; e < 4; e++) acc[t][e] = 0.0f;

        for (int k0 = 0; k0 < HD; k0 += 8) {
            uint32_t a0 = qu[(m0 + gid)     * QSS + k0 + tig];
            uint32_t a1 = qu[(m0 + gid + 8) * QSS + k0 + tig];
            uint32_t a2 = qu[(m0 + gid)     * QSS + k0 + tig + 4];
            uint32_t a3 = qu[(m0 + gid + 8) * QSS + k0 + tig + 4];
            for (int t = 0; t < cnt; t++) {
                int n0 = 8 * jn[t];
                uint32_t b0 = ku[(n0 + gid) * KSS + k0 + tig];
                uint32_t b1 = ku[(n0 + gid) * KSS + k0 + tig + 4];
                mma_tf32(acc[t], a0, a1, a2, a3, b0, b1);
            }
        }

        const float scale = 0.17677669529663687f;   // 1/sqrt(32)
        for (int t = 0; t < cnt; t++) {
            int n0 = 8 * jn[t];
            int c  = n0 + 2 * tig;
            #pragma unroll
            for (int half = 0; half < 2; half++) {
                int row = m0 + gid + 8 * half;
                scb[row * SCS + c]     = __float_as_uint(acc[t][2 * half]     * scale);
                scb[row * SCS + c + 1] = __float_as_uint(acc[t][2 * half + 1] * scale);
            }
        }
    }
    __syncthreads();

    // ---------------- Phase 3: causal softmax (R11 verbatim) ----------------
    {
        for (int r = warp; r < TT; r += 8) {
            uint32_t* row = scb + r * SCS;
            bool v0 = (lane <= r);
            bool v1 = (lane + 32 <= r);
            float s0 = v0 ? __uint_as_float(row[lane])      : -1e30f;
            float s1 = v1 ? __uint_as_float(row[lane + 32]) : -1e30f;
            float m = fmaxf(s0, s1);
            #pragma unroll
            for (int off = 16; off > 0; off >>= 1)
                m = fmaxf(m, __shfl_xor_sync(0xffffffffu, m, off));
            float e0 = v0 ? __expf(s0 - m) : 0.0f;
            float e1 = v1 ? __expf(s1 - m) : 0.0f;
            float sum = e0 + e1;
            #pragma unroll
            for (int off = 16; off > 0; off >>= 1)
                sum += __shfl_xor_sync(0xffffffffu, sum, off);
            float inv = 1.0f / sum;
            row[lane]      = f2tf(e0 * inv);   // tf32(0) = 0 where masked
            row[lane + 32] = f2tf(e1 * inv);
        }
    }
    __syncthreads();

    // ---------------- Phase 4: out = P @ V (R11 verbatim) ----------------
    {
        const int i  = warp & 3;
        const int m0 = 16 * i;
        const int jb = warp >> 2;

        float acc[2][4];
        #pragma unroll
        for (int t = 0; t < 2; t++)
            #pragma unroll
            for (int e = 0; e < 4; e++) acc[t][e] = 0.0f;

        const int kend = 16 * i + 8;   // probs beyond are exact zeros
        for (int k0 = 0; k0 <= kend; k0 += 8) {
            uint32_t a0 = scb[(m0 + gid)     * SCS + k0 + tig];
            uint32_t a1 = scb[(m0 + gid + 8) * SCS + k0 + tig];
            uint32_t a2 = scb[(m0 + gid)     * SCS + k0 + tig + 4];
            uint32_t a3 = scb[(m0 + gid + 8) * SCS + k0 + tig + 4];
            #pragma unroll
            for (int t = 0; t < 2; t++) {
                int n0 = 8 * (jb + 2 * t);
                uint32_t b0 = vT[(n0 + gid) * VTS + k0 + tig];
                uint32_t b1 = vT[(n0 + gid) * VTS + k0 + tig + 4];
                mma_tf32(acc[t], a0, a1, a2, a3, b0, b1);
            }
        }

        float* ob = out + (size_t)b * (TT * HD);
        #pragma unroll
        for (int t = 0; t < 2; t++) {
            int n0 = 8 * (jb + 2 * t);
            int c  = n0 + 2 * tig;
            #pragma unroll
            for (int half = 0; half < 2; half++) {
                int row = m0 + gid + 8 * half;
                *reinterpret_cast<float2*>(ob + row * HD + c) =
                    make_float2(acc[t][2 * half], acc[t][2 * half + 1]);
            }
        }
    }
}

extern "C" void kernel_launch(void* const* d_in, const int* in_sizes, int n_in,
                              void* d_out, int out_size) {
    const float* x  = (const float*)d_in[0];
    const float* Wq = (const float*)d_in[1];
    const float* Wk = (const float*)d_in[2];
    const float* Wv = (const float*)d_in[3];
    float* out = (float*)d_out;

    const int B = in_sizes[0] / (TT * CC);   // 4096
    const size_t smem_bytes = SMEM_WORDS * sizeof(float);

    static_assert(4 * (SMEM_WORDS * sizeof(float) + 1024) <= 228 * 1024,
                  "4 CTAs/SM incl. per-CTA reserve");
    cudaFuncSetAttribute(head_attn_kernel,
                         cudaFuncAttributeMaxDynamicSharedMemorySize,
                         (int)smem_bytes);

    wtf_kernel<<<52, 256>>>(Wq, Wk, Wv);
    head_attn_kernel<<<B, NTHREADS, smem_bytes>>>(x, out);
}

// round 16
// speedup vs baseline: 1.1127x; 1.0348x over previous
#include <cuda_runtime.h>
#include <cstdint>

#define TT 64
#define CC 128
#define HD 32
#define NTHREADS 512   // 16 warps, 2 batches per CTA

// Bank rules (lane = 4*gid + tig); batch offsets all ≡ 0 (mod 32)
#define XHS 36     // x quarter tf32 [2][64][36]  (A)  extent 32 ✓
#define WHS 104    // W quarter tf32 [32][104]    (B)  extent 96 ✓
#define SCS 68     // scores/probs [2][64][68] (A, overlays staging region)
#define QSS 36     // q tf32 [2][64][36]  (A)
#define KSS 36     // k tf32 [2][64][36]  (B via n-major)
#define VTS 68     // vT tf32 [2][32][68] (B via n-major)

#define XBW 2304               // words per x/q/k batch plane (64*36)
#define VBW 2176               // words per vT batch plane (32*68)
#define SBW 4352               // words per sc batch plane (64*68)

#define OFF_XH 0               // staging: xh 2*2304=4608, Wh 3328 -> 7936
#define OFF_WH 4608
#define OFF_Q  8704            // sc overlay needs 2*4352=8704 >= 7936
#define OFF_K  (OFF_Q + 2 * XBW)    // 13312
#define OFF_VT (OFF_K + 2 * XBW)    // 17920
#define SMEM_WORDS (OFF_VT + 2 * VBW)   // 22272 words = 89088 B

__device__ __forceinline__ uint32_t f2tf(float f) {
    uint32_t u;
    asm("cvt.rna.tf32.f32 %0, %1;" : "=r"(u) : "f"(f));
    return u;
}
__device__ __forceinline__ void mma_tf32(float c[4],
                                         uint32_t a0, uint32_t a1, uint32_t a2, uint32_t a3,
                                         uint32_t b0, uint32_t b1) {
    asm("mma.sync.aligned.m16n8k8.row.col.f32.tf32.tf32.f32 "
        "{%0,%1,%2,%3},{%4,%5,%6,%7},{%8,%9},{%0,%1,%2,%3};"
        : "+f"(c[0]), "+f"(c[1]), "+f"(c[2]), "+f"(c[3])
        : "r"(a0), "r"(a1), "r"(a2), "r"(a3), "r"(b0), "r"(b1));
}

__global__ __launch_bounds__(NTHREADS, 2)
void head_attn_kernel(const float* __restrict__ x,
                      const float* __restrict__ Wq,
                      const float* __restrict__ Wk,
                      const float* __restrict__ Wv,
                      float* __restrict__ out) {
    extern __shared__ float smem[];
    uint32_t* xh  = reinterpret_cast<uint32_t*>(smem + OFF_XH);  // [2][64][36]
    uint32_t* Wh  = reinterpret_cast<uint32_t*>(smem + OFF_WH);  // [32][104]
    uint32_t* qu  = reinterpret_cast<uint32_t*>(smem + OFF_Q);   // [2][64][36]
    uint32_t* ku  = reinterpret_cast<uint32_t*>(smem + OFF_K);   // [2][64][36]
    uint32_t* vT  = reinterpret_cast<uint32_t*>(smem + OFF_VT);  // [2][32][68]
    uint32_t* scb = reinterpret_cast<uint32_t*>(smem);           // [2][64][68] overlay

    const int tid  = threadIdx.x;
    const int warp = tid >> 5;
    const int lane = tid & 31;
    const int gid  = lane >> 2;   // 0..7
    const int tig  = lane & 3;    // 0..3
    const long b2  = 2L * blockIdx.x;
    const float* xb = x + b2 * (TT * CC);   // 2 consecutive batches

    // ---------------- Phase 1: QKV for both batches, 4-stage K-quarter staging ----------------
    // M=128, N=96. warp: m-tile mt=warp&7 (batch mt>>2), n-group g=warp>>3 (6 n-tiles)
    {
        const int mt    = warp & 7;
        const int bt    = mt >> 2;
        const int m0    = (mt & 3) * 16;
        const int nbase = (warp >> 3) * 48;
        const uint32_t* xbt = xh + bt * XBW;

        float acc[6][4];
        #pragma unroll
        for (int j = 0; j < 6; j++)
            #pragma unroll
            for (int t = 0; t < 4; t++) acc[j][t] = 0.0f;

        #pragma unroll
        for (int s = 0; s < 4; s++) {
            if (s) __syncthreads();

            // stage x[both batches][:, 32s..32s+32) as tf32 [2][64][36]
            #pragma unroll
            for (int ii = 0; ii < 2; ii++) {
                int i = tid + ii * NTHREADS;          // 0..1023 uint4
                int idx = i * 4;
                int btl = idx >> 11;                  // 0..1
                int r   = (idx >> 5) & 63;
                int c   = idx & 31;
                float4 v4 = *reinterpret_cast<const float4*>(
                    xb + (long)btl * (TT * CC) + r * CC + 32 * s + c);
                *reinterpret_cast<uint4*>(xh + btl * XBW + r * XHS + c) =
                    make_uint4(f2tf(v4.x), f2tf(v4.y), f2tf(v4.z), f2tf(v4.w));
            }
            // stage W[32s..32s+32, :] as tf32 [32][104] (once per 2 batches)
            if (tid < 256) {
                int idx = tid * 4;
                int dd = idx >> 5, c = idx & 31;
                int gi = ((32 * s + dd) * HD + c) / 4;
                float4 vq = reinterpret_cast<const float4*>(Wq)[gi];
                float4 vk = reinterpret_cast<const float4*>(Wk)[gi];
                float4 vv = reinterpret_cast<const float4*>(Wv)[gi];
                *reinterpret_cast<uint4*>(Wh + dd * WHS + c) =
                    make_uint4(f2tf(vq.x), f2tf(vq.y), f2tf(vq.z), f2tf(vq.w));
                *reinterpret_cast<uint4*>(Wh + dd * WHS + 32 + c) =
                    make_uint4(f2tf(vk.x), f2tf(vk.y), f2tf(vk.z), f2tf(vk.w));
                *reinterpret_cast<uint4*>(Wh + dd * WHS + 64 + c) =
                    make_uint4(f2tf(vv.x), f2tf(vv.y), f2tf(vv.z), f2tf(vv.w));
            }
            __syncthreads();

            #pragma unroll
            for (int kk = 0; kk < 32; kk += 8) {
                uint32_t a0 = xbt[(m0 + gid)     * XHS + kk + tig];
                uint32_t a1 = xbt[(m0 + gid + 8) * XHS + kk + tig];
                uint32_t a2 = xbt[(m0 + gid)     * XHS + kk + tig + 4];
                uint32_t a3 = xbt[(m0 + gid + 8) * XHS + kk + tig + 4];
                #pragma unroll
                for (int j = 0; j < 6; j++) {
                    int n0 = nbase + 8 * j;
                    uint32_t b0 = Wh[(kk + tig)     * WHS + n0 + gid];
                    uint32_t b1 = Wh[(kk + tig + 4) * WHS + n0 + gid];
                    mma_tf32(acc[j], a0, a1, a2, a3, b0, b1);
                }
            }
        }

        // scatter as tf32 into per-batch q/k/vT
        #pragma unroll
        for (int j = 0; j < 6; j++) {
            int n0 = nbase + 8 * j;
            int c  = n0 + 2 * tig;
            #pragma unroll
            for (int half = 0; half < 2; half++) {
                int row = m0 + gid + 8 * half;
                uint32_t u0 = f2tf(acc[j][2 * half]);
                uint32_t u1 = f2tf(acc[j][2 * half + 1]);
                if (n0 < 32) {
                    qu[bt * XBW + row * QSS + c]     = u0;
                    qu[bt * XBW + row * QSS + c + 1] = u1;
                } else if (n0 < 64) {
                    ku[bt * XBW + row * KSS + (c - 32)] = u0;
                    ku[bt * XBW + row * KSS + (c - 31)] = u1;
                } else {
                    vT[bt * VBW + (c - 64) * VTS + row] = u0;
                    vT[bt * VBW + (c - 63) * VTS + row] = u1;
                }
            }
        }
    }
    __syncthreads();

    // ---------------- Phase 2: scores, batch-paired balance (max 3 tiles/warp) ----------------
    // warp w: jb4 = w&3, i = (w>>2)&3; handles (batch0, i) and (batch1, 3-i),
    // j in {jb4, jb4+4} with j <= 2*it+1. Coverage exact, totals 2-3 tiles/warp.
    {
        const int jb4 = warp & 3;
        const int ib  = (warp >> 2) & 3;
        const float scale = 0.17677669529663687f;   // 1/sqrt(32)

        #pragma unroll
        for (int p = 0; p < 2; p++) {
            const int bt = p;
            const int it = p ? (3 - ib) : ib;
            const int m0 = 16 * it;
            int nj[2], cnt = 0;
            #pragma unroll
            for (int t = 0; t < 2; t++) {
                int j = jb4 + 4 * t;
                if (j <= 2 * it + 1) nj[cnt++] = j;
            }
            if (cnt == 0) continue;

            const uint32_t* qb = qu + bt * XBW;
            const uint32_t* kb = ku + bt * XBW;
            float acc[2][4];
            #pragma unroll
            for (int t = 0; t < 2; t++)
                #pragma unroll
                for (int e = 0; e < 4; e++) acc[t][e] = 0.0f;

            for (int k0 = 0; k0 < HD; k0 += 8) {
                uint32_t a0 = qb[(m0 + gid)     * QSS + k0 + tig];
                uint32_t a1 = qb[(m0 + gid + 8) * QSS + k0 + tig];
                uint32_t a2 = qb[(m0 + gid)     * QSS + k0 + tig + 4];
                uint32_t a3 = qb[(m0 + gid + 8) * QSS + k0 + tig + 4];
                for (int t = 0; t < cnt; t++) {
                    int n0 = 8 * nj[t];
                    uint32_t b0 = kb[(n0 + gid) * KSS + k0 + tig];
                    uint32_t b1 = kb[(n0 + gid) * KSS + k0 + tig + 4];
                    mma_tf32(acc[t], a0, a1, a2, a3, b0, b1);
                }
            }

            for (int t = 0; t < cnt; t++) {
                int n0 = 8 * nj[t];
                int c  = n0 + 2 * tig;
                #pragma unroll
                for (int half = 0; half < 2; half++) {
                    int row = m0 + gid + 8 * half;
                    scb[bt * SBW + row * SCS + c] =
                        __float_as_uint(acc[t][2 * half] * scale);
                    scb[bt * SBW + row * SCS + c + 1] =
                        __float_as_uint(acc[t][2 * half + 1] * scale);
                }
            }
        }
    }
    __syncthreads();

    // ---------------- Phase 3: causal softmax, 128 rows over 16 warps ----------------
    {
        for (int rr = warp; rr < 2 * TT; rr += 16) {
            int bt = rr >> 6;
            int r  = rr & 63;
            uint32_t* row = scb + bt * SBW + r * SCS;
            bool v0 = (lane <= r);
            bool v1 = (lane + 32 <= r);
            float s0 = v0 ? __uint_as_float(row[lane])      : -1e30f;
            float s1 = v1 ? __uint_as_float(row[lane + 32]) : -1e30f;
            float m = fmaxf(s0, s1);
            #pragma unroll
            for (int off = 16; off > 0; off >>= 1)
                m = fmaxf(m, __shfl_xor_sync(0xffffffffu, m, off));
            float e0 = v0 ? __expf(s0 - m) : 0.0f;
            float e1 = v1 ? __expf(s1 - m) : 0.0f;
            float sum = e0 + e1;
            #pragma unroll
            for (int off = 16; off > 0; off >>= 1)
                sum += __shfl_xor_sync(0xffffffffu, sum, off);
            float inv = 1.0f / sum;
            row[lane]      = f2tf(e0 * inv);   // tf32(0) = 0 where masked
            row[lane + 32] = f2tf(e1 * inv);
        }
    }
    __syncthreads();

    // ---------------- Phase 4: out = P @ V, batch-paired (exactly 10 k-steps/warp) ----------------
    // warp w: nt = w&3, i = (w>>2)&3; handles (batch0, i, nt) and (batch1, 3-i, nt).
    {
        const int nt = warp & 3;
        const int ib = (warp >> 2) & 3;

        #pragma unroll
        for (int p = 0; p < 2; p++) {
            const int bt = p;
            const int it = p ? (3 - ib) : ib;
            const int m0 = 16 * it;
            const int n0 = 8 * nt;
            const uint32_t* sb = scb + bt * SBW;
            const uint32_t* vb = vT + bt * VBW;

            float acc[4] = {0.f, 0.f, 0.f, 0.f};
            const int kend = 16 * it + 8;   // probs beyond are exact zeros
            for (int k0 = 0; k0 <= kend; k0 += 8) {
                uint32_t a0 = sb[(m0 + gid)     * SCS + k0 + tig];
                uint32_t a1 = sb[(m0 + gid + 8) * SCS + k0 + tig];
                uint32_t a2 = sb[(m0 + gid)     * SCS + k0 + tig + 4];
                uint32_t a3 = sb[(m0 + gid + 8) * SCS + k0 + tig + 4];
                uint32_t b0 = vb[(n0 + gid) * VTS + k0 + tig];
                uint32_t b1 = vb[(n0 + gid) * VTS + k0 + tig + 4];
                mma_tf32(acc, a0, a1, a2, a3, b0, b1);
            }

            float* ob = out + (b2 + bt) * (TT * HD);
            int c = n0 + 2 * tig;
            #pragma unroll
            for (int half = 0; half < 2; half++) {
                int row = m0 + gid + 8 * half;
                *reinterpret_cast<float2*>(ob + row * HD + c) =
                    make_float2(acc[2 * half], acc[2 * half + 1]);
            }
        }
    }
}

extern "C" void kernel_launch(void* const* d_in, const int* in_sizes, int n_in,
                              void* d_out, int out_size) {
    const float* x  = (const float*)d_in[0];
    const float* Wq = (const float*)d_in[1];
    const float* Wk = (const float*)d_in[2];
    const float* Wv = (const float*)d_in[3];
    float* out = (float*)d_out;

    const int B = in_sizes[0] / (TT * CC);   // 4096
    const size_t smem_bytes = SMEM_WORDS * sizeof(float);

    static_assert(2 * (SMEM_WORDS * sizeof(float) + 1024) <= 228 * 1024,
                  "2 CTAs/SM incl. per-CTA reserve");
    cudaFuncSetAttribute(head_attn_kernel,
                         cudaFuncAttributeMaxDynamicSharedMemorySize,
                         (int)smem_bytes);

    head_attn_kernel<<<B / 2, NTHREADS, smem_bytes>>>(x, Wq, Wk, Wv, out);
}